// round 15
// baseline (speedup 1.0000x reference)
#include <cuda_runtime.h>
#include <cuda_bf16.h>
#include <cstdint>
#include <math_constants.h>

#define BB   4
#define SS   4096
#define NC   8192
#define CCH  512
#define CSD  256
#define KTOT 768
#define BS   (BB * SS)
#define NSPLIT 32
#define REFS_PER_SPLIT (NC / NSPLIT)           // 256
#define PAIRS_PER_SPLIT (REFS_PER_SPLIT / 2)   // 128
#define WREFS 64
#define WINS_PER_SPLIT (REFS_PER_SPLIT / WREFS) // 4

// ---------------- device scratch ----------------
__device__ __align__(16) float  g_Acat[CSD * KTOT];
__device__ float  g_bias[CSD];
__device__ float4 g_refpack[BB * NC];
__device__ float4 g_refA[BB * NC / 2];
__device__ float4 g_refB[BB * NC / 2];
__device__ __align__(16) float g_featT[(size_t)BB * NC * CCH];
__device__ __align__(16) float g_seedT[(size_t)BB * SS * CSD];
__device__ int    g_idx[BS];
__device__ float  g_pd2[NSPLIT * BS];
__device__ int    g_pwin[NSPLIT * BS];

// ---------------- PTX helpers ----------------
__device__ __forceinline__ uint32_t smem_u32(const void *p) {
    uint32_t a;
    asm("{ .reg .u64 t; cvta.to.shared.u64 t, %1; cvt.u32.u64 %0, t; }" : "=r"(a) : "l"(p));
    return a;
}
__device__ __forceinline__ float f2tf32(float x) {
    uint32_t u;
    asm("cvt.rna.tf32.f32 %0, %1;" : "=r"(u) : "f"(x));
    return __uint_as_float(u);
}
__device__ __forceinline__ void cp16(uint32_t dst, const void *src) {
    asm volatile("cp.async.cg.shared.global [%0], [%1], 16;" :: "r"(dst), "l"(src) : "memory");
}
__device__ __forceinline__ void cp_commit() {
    asm volatile("cp.async.commit_group;" ::: "memory");
}
template <int N> __device__ __forceinline__ void cp_waitN() {
    asm volatile("cp.async.wait_group %0;" :: "n"(N) : "memory");
}
__device__ __forceinline__ void ldsm4(uint32_t &r0, uint32_t &r1, uint32_t &r2, uint32_t &r3,
                                      uint32_t addr) {
    asm volatile("ldmatrix.sync.aligned.m8n8.x4.shared.b16 {%0,%1,%2,%3}, [%4];"
                 : "=r"(r0), "=r"(r1), "=r"(r2), "=r"(r3) : "r"(addr));
}
__device__ __forceinline__ void mma_tf32(float *d, const uint32_t *a, const uint32_t *b) {
    asm volatile(
        "mma.sync.aligned.m16n8k8.row.col.f32.tf32.tf32.f32 "
        "{%0,%1,%2,%3}, {%4,%5,%6,%7}, {%8,%9}, {%0,%1,%2,%3};"
        : "+f"(d[0]), "+f"(d[1]), "+f"(d[2]), "+f"(d[3])
        : "r"(a[0]), "r"(a[1]), "r"(a[2]), "r"(a[3]), "r"(b[0]), "r"(b[1]));
}
__device__ __forceinline__ float2 ffma2(float2 a, float2 b, float2 c) {
    unsigned long long ua = *reinterpret_cast<unsigned long long *>(&a);
    unsigned long long ub = *reinterpret_cast<unsigned long long *>(&b);
    unsigned long long uc = *reinterpret_cast<unsigned long long *>(&c);
    unsigned long long ud;
    asm("fma.rn.f32x2 %0, %1, %2, %3;" : "=l"(ud) : "l"(ua), "l"(ub), "l"(uc));
    return *reinterpret_cast<float2 *>(&ud);
}

// ---------------- kernel: combine weights (tf32-rounded) -------------------
__global__ void prep_weights(const float *__restrict__ Wcp,
                             const float *__restrict__ Wsp,
                             const float *__restrict__ bseed,
                             const float *__restrict__ bconc) {
    __shared__ float w2[8][256];
    const int o0 = blockIdx.x * 8;
    const int t  = threadIdx.x;  // 512
    for (int i = t; i < 8 * 256; i += 512) {
        int oi = i >> 8, j = i & 255;
        w2[oi][j] = Wcp[(o0 + oi) * 512 + 256 + j];
    }
    for (int i = t; i < 8 * 256; i += 512) {
        int oi = i >> 8, c = i & 255;
        g_Acat[(o0 + oi) * KTOT + c] = f2tf32(Wcp[(o0 + oi) * 512 + c]);
    }
    __syncthreads();
    const int c = t;
    float acc[8];
#pragma unroll
    for (int oi = 0; oi < 8; oi++) acc[oi] = 0.f;
    for (int j = 0; j < 256; j++) {
        float v = Wsp[j * 512 + c];
#pragma unroll
        for (int oi = 0; oi < 8; oi++) acc[oi] = fmaf(w2[oi][j], v, acc[oi]);
    }
#pragma unroll
    for (int oi = 0; oi < 8; oi++)
        g_Acat[(o0 + oi) * KTOT + 256 + c] = f2tf32(acc[oi]);
    if (t < 8) {
        float bb = bconc[o0 + t];
        for (int j = 0; j < 256; j++) bb = fmaf(w2[t][j], bseed[j], bb);
        g_bias[o0 + t] = bb;
    }
}

// ---------------- pack refs ----------------
__global__ void refpack_kernel(const float *__restrict__ ref_xyz) {
    int p = blockIdx.x * 256 + threadIdx.x;
    if (p < BB * NC / 2) {
        const float *rp = ref_xyz + (size_t)p * 6;
        float x0 = rp[0], y0 = rp[1], z0 = rp[2];
        float x1 = rp[3], y1 = rp[4], z1 = rp[5];
        float r20 = fmaf(x0, x0, fmaf(y0, y0, z0 * z0));
        float r21 = fmaf(x1, x1, fmaf(y1, y1, z1 * z1));
        g_refpack[2 * p + 0] = make_float4(x0, y0, z0, r20);
        g_refpack[2 * p + 1] = make_float4(x1, y1, z1, r21);
        g_refA[p] = make_float4(x0, x1, y0, y1);
        g_refB[p] = make_float4(z0, z1, r20, r21);
    }
}

// ---------------- 64x64 transpose, 128 threads (8 LDG in flight) ----------
template <int R, int N, bool TO_FEAT>
__global__ void transpose64(const float *__restrict__ src) {
    __shared__ float tile[64][65];
    float *dstg = TO_FEAT ? g_featT : g_seedT;
    const int n0 = blockIdx.x * 64, r0 = blockIdx.y * 64, b = blockIdx.z;
    const int tx = threadIdx.x, ty = threadIdx.y;  // (16,8)
    const float *s = src + (size_t)b * R * N;
    float *d = dstg + (size_t)b * N * R;
    float4 v[8];
#pragma unroll
    for (int j = 0; j < 8; j++)
        v[j] = *(const float4 *)(s + (size_t)(r0 + ty + j * 8) * N + n0 + tx * 4);
#pragma unroll
    for (int j = 0; j < 8; j++) {
        tile[ty + j * 8][tx * 4 + 0] = v[j].x;
        tile[ty + j * 8][tx * 4 + 1] = v[j].y;
        tile[ty + j * 8][tx * 4 + 2] = v[j].z;
        tile[ty + j * 8][tx * 4 + 3] = v[j].w;
    }
    __syncthreads();
#pragma unroll
    for (int j = 0; j < 8; j++) {
        const int n = ty + j * 8;
        float4 o = make_float4(f2tf32(tile[tx * 4 + 0][n]),
                               f2tf32(tile[tx * 4 + 1][n]),
                               f2tf32(tile[tx * 4 + 2][n]),
                               f2tf32(tile[tx * 4 + 3][n]));
        *(float4 *)(d + (size_t)(n0 + n) * R + r0 + tx * 4) = o;
    }
}

// ---------------- NN pass A: packed min over windows ----------------------
__global__ void nn_minpass(const float *__restrict__ query) {
    __shared__ float4 spA[PAIRS_PER_SPLIT];
    __shared__ float4 spB[PAIRS_PER_SPLIT];
    const int b  = blockIdx.z;
    const int sp = blockIdx.y;
    const int qb = blockIdx.x * 512;
    const int t  = threadIdx.x;

    if (t < PAIRS_PER_SPLIT) {
        spA[t] = g_refA[(b * NC / 2) + sp * PAIRS_PER_SPLIT + t];
        spB[t] = g_refB[(b * NC / 2) + sp * PAIRS_PER_SPLIT + t];
    }

    const int q0 = qb + t, q1 = qb + 256 + t;
    const float *qp0 = query + ((size_t)b * SS + q0) * 3;
    const float *qp1 = query + ((size_t)b * SS + q1) * 3;
    const float2 ax0 = make_float2(-2.f * qp0[0], -2.f * qp0[0]);
    const float2 ay0 = make_float2(-2.f * qp0[1], -2.f * qp0[1]);
    const float2 az0 = make_float2(-2.f * qp0[2], -2.f * qp0[2]);
    const float2 ax1 = make_float2(-2.f * qp1[0], -2.f * qp1[0]);
    const float2 ay1 = make_float2(-2.f * qp1[1], -2.f * qp1[1]);
    const float2 az1 = make_float2(-2.f * qp1[2], -2.f * qp1[2]);
    __syncthreads();

    float best0 = CUDART_INF_F, best1 = CUDART_INF_F;
    int win0 = 0, win1 = 0;

#pragma unroll
    for (int w = 0; w < WINS_PER_SPLIT; w++) {
        float2 wm0 = make_float2(CUDART_INF_F, CUDART_INF_F);
        float2 wm1 = make_float2(CUDART_INF_F, CUDART_INF_F);
#pragma unroll 8
        for (int i = 0; i < WREFS / 2; i++) {
            float4 A = spA[w * (WREFS / 2) + i];
            float4 B = spB[w * (WREFS / 2) + i];
            float2 xp = make_float2(A.x, A.y);
            float2 yp = make_float2(A.z, A.w);
            float2 zp = make_float2(B.x, B.y);
            float2 rp = make_float2(B.z, B.w);
            float2 d0 = ffma2(ax0, xp, ffma2(ay0, yp, ffma2(az0, zp, rp)));
            float2 d1 = ffma2(ax1, xp, ffma2(ay1, yp, ffma2(az1, zp, rp)));
            wm0.x = fminf(wm0.x, d0.x); wm0.y = fminf(wm0.y, d0.y);
            wm1.x = fminf(wm1.x, d1.x); wm1.y = fminf(wm1.y, d1.y);
        }
        float m0 = fminf(wm0.x, wm0.y);
        float m1 = fminf(wm1.x, wm1.y);
        if (m0 < best0) { best0 = m0; win0 = w; }
        if (m1 < best1) { best1 = m1; win1 = w; }
    }
    g_pd2 [sp * BS + b * SS + q0] = best0;
    g_pwin[sp * BS + b * SS + q0] = win0;
    g_pd2 [sp * BS + b * SS + q1] = best1;
    g_pwin[sp * BS + b * SS + q1] = win1;
}

// ---------------- NN resolve: warp per query, coalesced -------------------
__global__ void nn_resolve(const float *__restrict__ query) {
    const int gq   = blockIdx.x * 8 + (threadIdx.x >> 5);  // < BS
    const int lane = threadIdx.x & 31;
    const int b    = gq / SS;

    float best = CUDART_INF_F;
    int wstart = 0;
#pragma unroll
    for (int sp = 0; sp < NSPLIT; sp++) {
        float d = g_pd2[sp * BS + gq];
        if (d < best) { best = d; wstart = sp * REFS_PER_SPLIT + g_pwin[sp * BS + gq] * WREFS; }
    }
    const float *qp = query + (size_t)gq * 3;
    const float ax = -2.f * qp[0], ay = -2.f * qp[1], az = -2.f * qp[2];

    float4 r0 = g_refpack[b * NC + wstart + lane * 2];
    float4 r1 = g_refpack[b * NC + wstart + lane * 2 + 1];
    float d0 = fmaf(ax, r0.x, fmaf(ay, r0.y, fmaf(az, r0.z, r0.w)));
    float d1 = fmaf(ax, r1.x, fmaf(ay, r1.y, fmaf(az, r1.z, r1.w)));

    unsigned cand = 0xFFFFFFFFu;
    if (d1 == best) cand = lane * 2 + 1;
    if (d0 == best) cand = lane * 2;          // prefer earlier
    unsigned m = __reduce_min_sync(0xFFFFFFFFu, cand);
    if (lane == 0) g_idx[gq] = wstart + (int)m;
}

// ---------------- warp-MMA tf32 fused GEMM, 4-stage, 1 sync/iter ----------
#define W_TILE  (128 * 128)
#define X_TILE  (128 * 128)
#define STAGE   (W_TILE + X_TILE)    // 32768
#define NCH     24
#define NSTAGE  4

__global__ void __launch_bounds__(256, 1)
gemm_mma(float *__restrict__ out) {
    extern __shared__ char dsm[];
    __shared__ int   sidx[128];
    __shared__ float sbias[128];

    const int b   = blockIdx.z;
    const int m0  = blockIdx.y * 128;
    const int s0  = blockIdx.x * 128;
    const int tid = threadIdx.x;
    const int wid = tid >> 5, lane = tid & 31;

    const uint32_t base = smem_u32(dsm);

    if (tid < 128) {
        sidx[tid]  = g_idx[b * SS + s0 + tid];
        sbias[tid] = g_bias[m0 + tid];
    }
    __syncthreads();

    const float *seedTb = g_seedT + (size_t)b * SS * CSD;
    const float *featTb = g_featT + (size_t)b * NC * CCH;

    const int lrow  = tid >> 1;
    const int lhalf = (tid & 1) * 4;
    const int xidx  = sidx[lrow];
    const uint32_t woff = lrow * 128;
    const int lsx = lrow & 7;

    auto load_stage = [&](int c) {
        const int st = c % NSTAGE;
        const int k0 = c * 32;
        const uint32_t wb = base + st * STAGE;
        const uint32_t xb = wb + W_TILE;
        {
            const float *src = g_Acat + (size_t)(m0 + lrow) * KTOT + k0 + lhalf * 4;
#pragma unroll
            for (int i = 0; i < 4; i++) {
                int ch = lhalf + i;
                cp16(wb + woff + ((ch ^ lsx) << 4), src + i * 4);
            }
        }
        {
            const float *src = (k0 < 256)
                ? seedTb + (size_t)(s0 + lrow) * CSD + k0 + lhalf * 4
                : featTb + (size_t)xidx * CCH + (k0 - 256) + lhalf * 4;
#pragma unroll
            for (int i = 0; i < 4; i++) {
                int ch = lhalf + i;
                cp16(xb + woff + ((ch ^ lsx) << 4), src + i * 4);
            }
        }
        cp_commit();
    };

    const int td    = lane >> 3;
    const int a_row = (td & 1) * 8 + (lane & 7);
    const int a_ch  = td >> 1;
    const int b_row = (td >> 1) * 8 + (lane & 7);
    const int b_ch  = td & 1;
    const int sxa = a_row & 7;
    const int sxb = b_row & 7;
    const int wm0 = (wid & 1) * 64;
    const int ws0 = (wid >> 1) * 32;
    uint32_t aoff[4], boff[2];
#pragma unroll
    for (int fi = 0; fi < 4; fi++) aoff[fi] = (wm0 + fi * 16 + a_row) * 128;
#pragma unroll
    for (int fjh = 0; fjh < 2; fjh++) boff[fjh] = (ws0 + fjh * 16 + b_row) * 128;

    float acc[4][4][4];
#pragma unroll
    for (int i = 0; i < 4; i++)
#pragma unroll
        for (int j = 0; j < 4; j++)
#pragma unroll
            for (int r = 0; r < 4; r++) acc[i][j][r] = 0.f;

    load_stage(0);
    load_stage(1);

    for (int c = 0; c < NCH; c++) {
        // slot(c+2) == slot(c-2): the barrier in iteration c-1 already
        // guaranteed every warp finished compute(c-2) -> safe to overwrite.
        if (c + 2 < NCH) { load_stage(c + 2); cp_waitN<2>(); }
        else if (c + 1 < NCH) cp_waitN<1>();
        else cp_waitN<0>();
        __syncthreads();   // stage c visible to all warps

        const int st = c % NSTAGE;
        const uint32_t wb = base + st * STAGE;
        const uint32_t xb = wb + W_TILE;

#pragma unroll
        for (int ks = 0; ks < 4; ks++) {
            const uint32_t cha = ((2 * ks + a_ch) ^ sxa) << 4;
            const uint32_t chb = ((2 * ks + b_ch) ^ sxb) << 4;
            uint32_t areg[4][4];
#pragma unroll
            for (int fi = 0; fi < 4; fi++)
                ldsm4(areg[fi][0], areg[fi][1], areg[fi][2], areg[fi][3],
                      wb + aoff[fi] + cha);
            uint32_t breg[8];
#pragma unroll
            for (int fjh = 0; fjh < 2; fjh++)
                ldsm4(breg[fjh * 4 + 0], breg[fjh * 4 + 1],
                      breg[fjh * 4 + 2], breg[fjh * 4 + 3],
                      xb + boff[fjh] + chb);
#pragma unroll
            for (int fi = 0; fi < 4; fi++)
#pragma unroll
                for (int fj = 0; fj < 4; fj++)
                    mma_tf32(acc[fi][fj], areg[fi], breg + fj * 2);
        }
    }

    // ---- epilogue
#pragma unroll
    for (int fi = 0; fi < 4; fi++) {
        const int ml = wm0 + fi * 16 + (lane >> 2);
        const int mh = ml + 8;
        const float bl = sbias[ml], bh = sbias[mh];
        float *olo = out + ((size_t)b * CSD + m0 + ml) * SS + s0;
        float *ohi = out + ((size_t)b * CSD + m0 + mh) * SS + s0;
#pragma unroll
        for (int fj = 0; fj < 4; fj++) {
            const int s = ws0 + fj * 8 + 2 * (lane & 3);
            *(float2 *)(olo + s) = make_float2(acc[fi][fj][0] + bl, acc[fi][fj][1] + bl);
            *(float2 *)(ohi + s) = make_float2(acc[fi][fj][2] + bh, acc[fi][fj][3] + bh);
        }
    }
}

// ---------------- launch (nn_minpass is 4th -> gets profiled) -------------
extern "C" void kernel_launch(void *const *d_in, const int *in_sizes, int n_in,
                              void *d_out, int out_size) {
    const float *query  = (const float *)d_in[0];
    const float *refxyz = (const float *)d_in[1];
    const float *reffeat= (const float *)d_in[2];
    const float *seed   = (const float *)d_in[3];
    const float *Wsp    = (const float *)d_in[4];
    const float *bseed  = (const float *)d_in[5];
    const float *Wcp    = (const float *)d_in[6];
    const float *bconc  = (const float *)d_in[7];
    float *out = (float *)d_out;

    cudaFuncSetAttribute(gemm_mma, cudaFuncAttributeMaxDynamicSharedMemorySize,
                         NSTAGE * STAGE);

    prep_weights<<<32, 512>>>(Wcp, Wsp, bseed, bconc);
    refpack_kernel<<<(BB * NC / 2 + 255) / 256, 256>>>(refxyz);
    transpose64<CCH, NC, true><<<dim3(NC / 64, CCH / 64, BB), dim3(16, 8)>>>(reffeat);
    nn_minpass<<<dim3(SS / 512, NSPLIT, BB), 256>>>(query);
    transpose64<CSD, SS, false><<<dim3(SS / 64, CSD / 64, BB), dim3(16, 8)>>>(seed);
    nn_resolve<<<BS / 8, 256>>>(query);
    gemm_mma<<<dim3(SS / 128, CSD / 128, BB), 256, NSTAGE * STAGE>>>(out);
}

// round 16
// speedup vs baseline: 1.3817x; 1.3817x over previous
#include <cuda_runtime.h>
#include <cuda_bf16.h>
#include <cstdint>
#include <math_constants.h>

#define BB   4
#define SS   4096
#define NC   8192
#define CCH  512
#define CSD  256
#define KTOT 768
#define BS   (BB * SS)
#define NSPLIT 8
#define REFS_PER_SPLIT (NC / NSPLIT)           // 1024
#define PAIRS_PER_SPLIT (REFS_PER_SPLIT / 2)   // 512
#define WREFS 64
#define WINS_PER_SPLIT (REFS_PER_SPLIT / WREFS) // 16

// ---------------- device scratch ----------------
__device__ __align__(16) float  g_Acat[CSD * KTOT];
__device__ float  g_bias[CSD];
__device__ float4 g_refpack[BB * NC];
__device__ float4 g_refA[BB * NC / 2];
__device__ float4 g_refB[BB * NC / 2];
__device__ __align__(16) float g_featT[(size_t)BB * NC * CCH];
__device__ __align__(16) float g_seedT[(size_t)BB * SS * CSD];
__device__ int    g_idx[BS];
__device__ float  g_pd2[NSPLIT * BS];
__device__ int    g_pwin[NSPLIT * BS];

// ---------------- PTX helpers ----------------
__device__ __forceinline__ uint32_t smem_u32(const void *p) {
    uint32_t a;
    asm("{ .reg .u64 t; cvta.to.shared.u64 t, %1; cvt.u32.u64 %0, t; }" : "=r"(a) : "l"(p));
    return a;
}
__device__ __forceinline__ float f2tf32(float x) {
    uint32_t u;
    asm("cvt.rna.tf32.f32 %0, %1;" : "=r"(u) : "f"(x));
    return __uint_as_float(u);
}
__device__ __forceinline__ void cp16(uint32_t dst, const void *src) {
    asm volatile("cp.async.cg.shared.global [%0], [%1], 16;" :: "r"(dst), "l"(src) : "memory");
}
__device__ __forceinline__ void cp_commit() {
    asm volatile("cp.async.commit_group;" ::: "memory");
}
template <int N> __device__ __forceinline__ void cp_waitN() {
    asm volatile("cp.async.wait_group %0;" :: "n"(N) : "memory");
}
__device__ __forceinline__ void ldsm4(uint32_t &r0, uint32_t &r1, uint32_t &r2, uint32_t &r3,
                                      uint32_t addr) {
    asm volatile("ldmatrix.sync.aligned.m8n8.x4.shared.b16 {%0,%1,%2,%3}, [%4];"
                 : "=r"(r0), "=r"(r1), "=r"(r2), "=r"(r3) : "r"(addr));
}
__device__ __forceinline__ void mma_tf32(float *d, const uint32_t *a, const uint32_t *b) {
    asm volatile(
        "mma.sync.aligned.m16n8k8.row.col.f32.tf32.tf32.f32 "
        "{%0,%1,%2,%3}, {%4,%5,%6,%7}, {%8,%9}, {%0,%1,%2,%3};"
        : "+f"(d[0]), "+f"(d[1]), "+f"(d[2]), "+f"(d[3])
        : "r"(a[0]), "r"(a[1]), "r"(a[2]), "r"(a[3]), "r"(b[0]), "r"(b[1]));
}
__device__ __forceinline__ float2 ffma2(float2 a, float2 b, float2 c) {
    unsigned long long ua = *reinterpret_cast<unsigned long long *>(&a);
    unsigned long long ub = *reinterpret_cast<unsigned long long *>(&b);
    unsigned long long uc = *reinterpret_cast<unsigned long long *>(&c);
    unsigned long long ud;
    asm("fma.rn.f32x2 %0, %1, %2, %3;" : "=l"(ud) : "l"(ua), "l"(ub), "l"(uc));
    return *reinterpret_cast<float2 *>(&ud);
}

// ---------------- kernel: combine weights (tf32-rounded) -------------------
__global__ void prep_weights(const float *__restrict__ Wcp,
                             const float *__restrict__ Wsp,
                             const float *__restrict__ bseed,
                             const float *__restrict__ bconc) {
    __shared__ float w2[8][256];
    const int o0 = blockIdx.x * 8;
    const int t  = threadIdx.x;  // 512
    for (int i = t; i < 8 * 256; i += 512) {
        int oi = i >> 8, j = i & 255;
        w2[oi][j] = Wcp[(o0 + oi) * 512 + 256 + j];
    }
    for (int i = t; i < 8 * 256; i += 512) {
        int oi = i >> 8, c = i & 255;
        g_Acat[(o0 + oi) * KTOT + c] = f2tf32(Wcp[(o0 + oi) * 512 + c]);
    }
    __syncthreads();
    const int c = t;
    float acc[8];
#pragma unroll
    for (int oi = 0; oi < 8; oi++) acc[oi] = 0.f;
    for (int j = 0; j < 256; j++) {
        float v = Wsp[j * 512 + c];
#pragma unroll
        for (int oi = 0; oi < 8; oi++) acc[oi] = fmaf(w2[oi][j], v, acc[oi]);
    }
#pragma unroll
    for (int oi = 0; oi < 8; oi++)
        g_Acat[(o0 + oi) * KTOT + 256 + c] = f2tf32(acc[oi]);
    if (t < 8) {
        float bb = bconc[o0 + t];
        for (int j = 0; j < 256; j++) bb = fmaf(w2[t][j], bseed[j], bb);
        g_bias[o0 + t] = bb;
    }
}

// ---------------- pack refs ----------------
__global__ void refpack_kernel(const float *__restrict__ ref_xyz) {
    int p = blockIdx.x * 256 + threadIdx.x;
    if (p < BB * NC / 2) {
        const float *rp = ref_xyz + (size_t)p * 6;
        float x0 = rp[0], y0 = rp[1], z0 = rp[2];
        float x1 = rp[3], y1 = rp[4], z1 = rp[5];
        float r20 = fmaf(x0, x0, fmaf(y0, y0, z0 * z0));
        float r21 = fmaf(x1, x1, fmaf(y1, y1, z1 * z1));
        g_refpack[2 * p + 0] = make_float4(x0, y0, z0, r20);
        g_refpack[2 * p + 1] = make_float4(x1, y1, z1, r21);
        g_refA[p] = make_float4(x0, x1, y0, y1);
        g_refB[p] = make_float4(z0, z1, r20, r21);
    }
}

// ---------------- 64x64 transpose, 128 threads (8 LDG in flight) ----------
template <int R, int N, bool TO_FEAT>
__global__ void transpose64(const float *__restrict__ src) {
    __shared__ float tile[64][65];
    float *dstg = TO_FEAT ? g_featT : g_seedT;
    const int n0 = blockIdx.x * 64, r0 = blockIdx.y * 64, b = blockIdx.z;
    const int tx = threadIdx.x, ty = threadIdx.y;  // (16,8)
    const float *s = src + (size_t)b * R * N;
    float *d = dstg + (size_t)b * N * R;
    float4 v[8];
#pragma unroll
    for (int j = 0; j < 8; j++)
        v[j] = *(const float4 *)(s + (size_t)(r0 + ty + j * 8) * N + n0 + tx * 4);
#pragma unroll
    for (int j = 0; j < 8; j++) {
        tile[ty + j * 8][tx * 4 + 0] = v[j].x;
        tile[ty + j * 8][tx * 4 + 1] = v[j].y;
        tile[ty + j * 8][tx * 4 + 2] = v[j].z;
        tile[ty + j * 8][tx * 4 + 3] = v[j].w;
    }
    __syncthreads();
#pragma unroll
    for (int j = 0; j < 8; j++) {
        const int n = ty + j * 8;
        float4 o = make_float4(f2tf32(tile[tx * 4 + 0][n]),
                               f2tf32(tile[tx * 4 + 1][n]),
                               f2tf32(tile[tx * 4 + 2][n]),
                               f2tf32(tile[tx * 4 + 3][n]));
        *(float4 *)(d + (size_t)(n0 + n) * R + r0 + tx * 4) = o;
    }
}

// ---------------- NN pass A: packed min over windows (R13-proven) ---------
__global__ void nn_minpass(const float *__restrict__ query) {
    __shared__ float4 spA[PAIRS_PER_SPLIT];
    __shared__ float4 spB[PAIRS_PER_SPLIT];
    const int b  = blockIdx.z;
    const int sp = blockIdx.y;
    const int qb = blockIdx.x * 512;
    const int t  = threadIdx.x;

    for (int i = t; i < PAIRS_PER_SPLIT; i += 256) {
        spA[i] = g_refA[(b * NC / 2) + sp * PAIRS_PER_SPLIT + i];
        spB[i] = g_refB[(b * NC / 2) + sp * PAIRS_PER_SPLIT + i];
    }

    const int q0 = qb + t, q1 = qb + 256 + t;
    const float *qp0 = query + ((size_t)b * SS + q0) * 3;
    const float *qp1 = query + ((size_t)b * SS + q1) * 3;
    const float2 ax0 = make_float2(-2.f * qp0[0], -2.f * qp0[0]);
    const float2 ay0 = make_float2(-2.f * qp0[1], -2.f * qp0[1]);
    const float2 az0 = make_float2(-2.f * qp0[2], -2.f * qp0[2]);
    const float2 ax1 = make_float2(-2.f * qp1[0], -2.f * qp1[0]);
    const float2 ay1 = make_float2(-2.f * qp1[1], -2.f * qp1[1]);
    const float2 az1 = make_float2(-2.f * qp1[2], -2.f * qp1[2]);
    __syncthreads();

    float best0 = CUDART_INF_F, best1 = CUDART_INF_F;
    int win0 = 0, win1 = 0;

    for (int w = 0; w < WINS_PER_SPLIT; w++) {
        float2 wm0 = make_float2(CUDART_INF_F, CUDART_INF_F);
        float2 wm1 = make_float2(CUDART_INF_F, CUDART_INF_F);
#pragma unroll 8
        for (int i = 0; i < WREFS / 2; i++) {
            float4 A = spA[w * (WREFS / 2) + i];
            float4 B = spB[w * (WREFS / 2) + i];
            float2 xp = make_float2(A.x, A.y);
            float2 yp = make_float2(A.z, A.w);
            float2 zp = make_float2(B.x, B.y);
            float2 rp = make_float2(B.z, B.w);
            float2 d0 = ffma2(ax0, xp, ffma2(ay0, yp, ffma2(az0, zp, rp)));
            float2 d1 = ffma2(ax1, xp, ffma2(ay1, yp, ffma2(az1, zp, rp)));
            wm0.x = fminf(wm0.x, d0.x); wm0.y = fminf(wm0.y, d0.y);
            wm1.x = fminf(wm1.x, d1.x); wm1.y = fminf(wm1.y, d1.y);
        }
        float m0 = fminf(wm0.x, wm0.y);
        float m1 = fminf(wm1.x, wm1.y);
        if (m0 < best0) { best0 = m0; win0 = w; }
        if (m1 < best1) { best1 = m1; win1 = w; }
    }
    g_pd2 [sp * BS + b * SS + q0] = best0;
    g_pwin[sp * BS + b * SS + q0] = win0;
    g_pd2 [sp * BS + b * SS + q1] = best1;
    g_pwin[sp * BS + b * SS + q1] = win1;
}

// ---------------- NN resolve: warp per query, coalesced -------------------
__global__ void nn_resolve(const float *__restrict__ query) {
    const int gq   = blockIdx.x * 8 + (threadIdx.x >> 5);  // < BS
    const int lane = threadIdx.x & 31;
    const int b    = gq / SS;

    float best = CUDART_INF_F;
    int wstart = 0;
#pragma unroll
    for (int sp = 0; sp < NSPLIT; sp++) {
        float d = g_pd2[sp * BS + gq];
        if (d < best) { best = d; wstart = sp * REFS_PER_SPLIT + g_pwin[sp * BS + gq] * WREFS; }
    }
    const float *qp = query + (size_t)gq * 3;
    const float ax = -2.f * qp[0], ay = -2.f * qp[1], az = -2.f * qp[2];

    float4 r0 = g_refpack[b * NC + wstart + lane * 2];
    float4 r1 = g_refpack[b * NC + wstart + lane * 2 + 1];
    float d0 = fmaf(ax, r0.x, fmaf(ay, r0.y, fmaf(az, r0.z, r0.w)));
    float d1 = fmaf(ax, r1.x, fmaf(ay, r1.y, fmaf(az, r1.z, r1.w)));

    unsigned cand = 0xFFFFFFFFu;
    if (d1 == best) cand = lane * 2 + 1;
    if (d0 == best) cand = lane * 2;          // prefer earlier
    unsigned m = __reduce_min_sync(0xFFFFFFFFu, cand);
    if (lane == 0) g_idx[gq] = wstart + (int)m;
}

// ---------------- warp-MMA tf32 fused GEMM, 512 threads, 3-stage ----------
// CTA tile 128m x 128s, 16 warps, warp tile 32x32 (4 warps/SMSP for latency
// hiding; acc only 32 regs/thread -> no spill).
#define W_TILE  (128 * 128)
#define X_TILE  (128 * 128)
#define STAGE   (W_TILE + X_TILE)    // 32768
#define NCH     24
#define NSTAGE  3

__global__ void __launch_bounds__(512, 1)
gemm_mma(float *__restrict__ out) {
    extern __shared__ char dsm[];
    __shared__ int   sidx[128];
    __shared__ float sbias[128];

    const int b   = blockIdx.z;
    const int m0  = blockIdx.y * 128;
    const int s0  = blockIdx.x * 128;
    const int tid = threadIdx.x;
    const int wid = tid >> 5, lane = tid & 31;

    const uint32_t base = smem_u32(dsm);

    if (tid < 128) {
        sidx[tid]  = g_idx[b * SS + s0 + tid];
        sbias[tid] = g_bias[m0 + tid];
    }
    __syncthreads();

    const float *seedTb = g_seedT + (size_t)b * SS * CSD;
    const float *featTb = g_featT + (size_t)b * NC * CCH;

    // loader: thread -> row tid>>2 (0..127), chunk pair (tid&3)*2
    const int lrow = tid >> 2;
    const int lch  = (tid & 3) * 2;
    const int xidx = sidx[lrow];
    const uint32_t woff = lrow * 128;
    const int lsx = lrow & 7;

    auto load_stage = [&](int c) {
        const int st = c % NSTAGE;
        const int k0 = c * 32;
        const uint32_t wb = base + st * STAGE;
        const uint32_t xb = wb + W_TILE;
        {
            const float *src = g_Acat + (size_t)(m0 + lrow) * KTOT + k0 + lch * 4;
#pragma unroll
            for (int i = 0; i < 2; i++) {
                int ch = lch + i;
                cp16(wb + woff + ((ch ^ lsx) << 4), src + i * 4);
            }
        }
        {
            const float *src = (k0 < 256)
                ? seedTb + (size_t)(s0 + lrow) * CSD + k0 + lch * 4
                : featTb + (size_t)xidx * CCH + (k0 - 256) + lch * 4;
#pragma unroll
            for (int i = 0; i < 2; i++) {
                int ch = lch + i;
                cp16(xb + woff + ((ch ^ lsx) << 4), src + i * 4);
            }
        }
        cp_commit();
    };

    // ldmatrix per-thread constants (proven mapping; only wm0/ws0 changed)
    const int td    = lane >> 3;
    const int a_row = (td & 1) * 8 + (lane & 7);
    const int a_ch  = td >> 1;
    const int b_row = (td >> 1) * 8 + (lane & 7);
    const int b_ch  = td & 1;
    const int sxa = a_row & 7;
    const int sxb = b_row & 7;
    const int wm0 = (wid & 3) * 32;      // 4 m-tiles of 32
    const int ws0 = (wid >> 2) * 32;     // 4 s-tiles of 32
    uint32_t aoff[2], boff[2];
#pragma unroll
    for (int fi = 0; fi < 2; fi++) aoff[fi] = (wm0 + fi * 16 + a_row) * 128;
#pragma unroll
    for (int fjh = 0; fjh < 2; fjh++) boff[fjh] = (ws0 + fjh * 16 + b_row) * 128;

    float acc[2][4][4];
#pragma unroll
    for (int i = 0; i < 2; i++)
#pragma unroll
        for (int j = 0; j < 4; j++)
#pragma unroll
            for (int r = 0; r < 4; r++) acc[i][j][r] = 0.f;

    load_stage(0);
    load_stage(1);

    for (int c = 0; c < NCH; c++) {
        __syncthreads();
        if (c + 2 < NCH) { load_stage(c + 2); cp_waitN<2>(); }
        else if (c + 1 < NCH) cp_waitN<1>();
        else cp_waitN<0>();
        __syncthreads();

        const int st = c % NSTAGE;
        const uint32_t wb = base + st * STAGE;
        const uint32_t xb = wb + W_TILE;

#pragma unroll
        for (int ks = 0; ks < 4; ks++) {
            const uint32_t cha = ((2 * ks + a_ch) ^ sxa) << 4;
            const uint32_t chb = ((2 * ks + b_ch) ^ sxb) << 4;
            uint32_t areg[2][4];
#pragma unroll
            for (int fi = 0; fi < 2; fi++)
                ldsm4(areg[fi][0], areg[fi][1], areg[fi][2], areg[fi][3],
                      wb + aoff[fi] + cha);
            uint32_t breg[8];
#pragma unroll
            for (int fjh = 0; fjh < 2; fjh++)
                ldsm4(breg[fjh * 4 + 0], breg[fjh * 4 + 1],
                      breg[fjh * 4 + 2], breg[fjh * 4 + 3],
                      xb + boff[fjh] + chb);
#pragma unroll
            for (int fi = 0; fi < 2; fi++)
#pragma unroll
                for (int fj = 0; fj < 4; fj++)
                    mma_tf32(acc[fi][fj], areg[fi], breg + fj * 2);
        }
    }

    // ---- epilogue
#pragma unroll
    for (int fi = 0; fi < 2; fi++) {
        const int ml = wm0 + fi * 16 + (lane >> 2);
        const int mh = ml + 8;
        const float bl = sbias[ml], bh = sbias[mh];
        float *olo = out + ((size_t)b * CSD + m0 + ml) * SS + s0;
        float *ohi = out + ((size_t)b * CSD + m0 + mh) * SS + s0;
#pragma unroll
        for (int fj = 0; fj < 4; fj++) {
            const int s = ws0 + fj * 8 + 2 * (lane & 3);
            *(float2 *)(olo + s) = make_float2(acc[fi][fj][0] + bl, acc[fi][fj][1] + bl);
            *(float2 *)(ohi + s) = make_float2(acc[fi][fj][2] + bh, acc[fi][fj][3] + bh);
        }
    }
}

// ---------------- launch (t_feat is 4th -> gets profiled) -----------------
extern "C" void kernel_launch(void *const *d_in, const int *in_sizes, int n_in,
                              void *d_out, int out_size) {
    const float *query  = (const float *)d_in[0];
    const float *refxyz = (const float *)d_in[1];
    const float *reffeat= (const float *)d_in[2];
    const float *seed   = (const float *)d_in[3];
    const float *Wsp    = (const float *)d_in[4];
    const float *bseed  = (const float *)d_in[5];
    const float *Wcp    = (const float *)d_in[6];
    const float *bconc  = (const float *)d_in[7];
    float *out = (float *)d_out;

    cudaFuncSetAttribute(gemm_mma, cudaFuncAttributeMaxDynamicSharedMemorySize,
                         NSTAGE * STAGE);

    prep_weights<<<32, 512>>>(Wcp, Wsp, bseed, bconc);
    refpack_kernel<<<(BB * NC / 2 + 255) / 256, 256>>>(refxyz);
    nn_minpass<<<dim3(SS / 512, NSPLIT, BB), 256>>>(query);
    transpose64<CCH, NC, true><<<dim3(NC / 64, CCH / 64, BB), dim3(16, 8)>>>(reffeat);
    transpose64<CSD, SS, false><<<dim3(SS / 64, CSD / 64, BB), dim3(16, 8)>>>(seed);
    nn_resolve<<<BS / 8, 256>>>(query);
    gemm_mma<<<dim3(SS / 128, CSD / 128, BB), 512, NSTAGE * STAGE>>>(out);
}

// round 17
// speedup vs baseline: 1.4138x; 1.0233x over previous
#include <cuda_runtime.h>
#include <cuda_bf16.h>
#include <cstdint>
#include <math_constants.h>

#define BB   4
#define SS   4096
#define NC   8192
#define CCH  512
#define CSD  256
#define KTOT 768
#define BS   (BB * SS)
#define NSPLIT 16
#define REFS_PER_SPLIT (NC / NSPLIT)            // 512
#define PAIRS_PER_SPLIT (REFS_PER_SPLIT / 2)    // 256
#define WREFS 64
#define WINS_PER_SPLIT (REFS_PER_SPLIT / WREFS) // 8
#define QPT 4                                    // queries per thread

// ---------------- device scratch ----------------
__device__ __align__(16) float  g_Acat[CSD * KTOT];
__device__ float  g_bias[CSD];
__device__ float4 g_refpack[BB * NC];
__device__ float4 g_refA[BB * NC / 2];
__device__ float4 g_refB[BB * NC / 2];
__device__ __align__(16) float g_featT[(size_t)BB * NC * CCH];
__device__ __align__(16) float g_seedT[(size_t)BB * SS * CSD];
__device__ int    g_idx[BS];
__device__ float  g_pd2[NSPLIT * BS];
__device__ int    g_pwin[NSPLIT * BS];

// ---------------- PTX helpers ----------------
__device__ __forceinline__ uint32_t smem_u32(const void *p) {
    uint32_t a;
    asm("{ .reg .u64 t; cvta.to.shared.u64 t, %1; cvt.u32.u64 %0, t; }" : "=r"(a) : "l"(p));
    return a;
}
__device__ __forceinline__ float f2tf32(float x) {
    uint32_t u;
    asm("cvt.rna.tf32.f32 %0, %1;" : "=r"(u) : "f"(x));
    return __uint_as_float(u);
}
__device__ __forceinline__ void cp16(uint32_t dst, const void *src) {
    asm volatile("cp.async.cg.shared.global [%0], [%1], 16;" :: "r"(dst), "l"(src) : "memory");
}
__device__ __forceinline__ void cp_commit() {
    asm volatile("cp.async.commit_group;" ::: "memory");
}
template <int N> __device__ __forceinline__ void cp_waitN() {
    asm volatile("cp.async.wait_group %0;" :: "n"(N) : "memory");
}
__device__ __forceinline__ void ldsm4(uint32_t &r0, uint32_t &r1, uint32_t &r2, uint32_t &r3,
                                      uint32_t addr) {
    asm volatile("ldmatrix.sync.aligned.m8n8.x4.shared.b16 {%0,%1,%2,%3}, [%4];"
                 : "=r"(r0), "=r"(r1), "=r"(r2), "=r"(r3) : "r"(addr));
}
__device__ __forceinline__ void mma_tf32(float *d, const uint32_t *a, const uint32_t *b) {
    asm volatile(
        "mma.sync.aligned.m16n8k8.row.col.f32.tf32.tf32.f32 "
        "{%0,%1,%2,%3}, {%4,%5,%6,%7}, {%8,%9}, {%0,%1,%2,%3};"
        : "+f"(d[0]), "+f"(d[1]), "+f"(d[2]), "+f"(d[3])
        : "r"(a[0]), "r"(a[1]), "r"(a[2]), "r"(a[3]), "r"(b[0]), "r"(b[1]));
}
__device__ __forceinline__ float2 ffma2(float2 a, float2 b, float2 c) {
    unsigned long long ua = *reinterpret_cast<unsigned long long *>(&a);
    unsigned long long ub = *reinterpret_cast<unsigned long long *>(&b);
    unsigned long long uc = *reinterpret_cast<unsigned long long *>(&c);
    unsigned long long ud;
    asm("fma.rn.f32x2 %0, %1, %2, %3;" : "=l"(ud) : "l"(ua), "l"(ub), "l"(uc));
    return *reinterpret_cast<float2 *>(&ud);
}

// ---------------- kernel: combine weights (tf32-rounded) -------------------
__global__ void prep_weights(const float *__restrict__ Wcp,
                             const float *__restrict__ Wsp,
                             const float *__restrict__ bseed,
                             const float *__restrict__ bconc) {
    __shared__ float w2[8][256];
    const int o0 = blockIdx.x * 8;
    const int t  = threadIdx.x;  // 512
    for (int i = t; i < 8 * 256; i += 512) {
        int oi = i >> 8, j = i & 255;
        w2[oi][j] = Wcp[(o0 + oi) * 512 + 256 + j];
    }
    for (int i = t; i < 8 * 256; i += 512) {
        int oi = i >> 8, c = i & 255;
        g_Acat[(o0 + oi) * KTOT + c] = f2tf32(Wcp[(o0 + oi) * 512 + c]);
    }
    __syncthreads();
    const int c = t;
    float acc[8];
#pragma unroll
    for (int oi = 0; oi < 8; oi++) acc[oi] = 0.f;
    for (int j = 0; j < 256; j++) {
        float v = Wsp[j * 512 + c];
#pragma unroll
        for (int oi = 0; oi < 8; oi++) acc[oi] = fmaf(w2[oi][j], v, acc[oi]);
    }
#pragma unroll
    for (int oi = 0; oi < 8; oi++)
        g_Acat[(o0 + oi) * KTOT + 256 + c] = f2tf32(acc[oi]);
    if (t < 8) {
        float bb = bconc[o0 + t];
        for (int j = 0; j < 256; j++) bb = fmaf(w2[t][j], bseed[j], bb);
        g_bias[o0 + t] = bb;
    }
}

// ---------------- pack refs ----------------
__global__ void refpack_kernel(const float *__restrict__ ref_xyz) {
    int p = blockIdx.x * 256 + threadIdx.x;
    if (p < BB * NC / 2) {
        const float *rp = ref_xyz + (size_t)p * 6;
        float x0 = rp[0], y0 = rp[1], z0 = rp[2];
        float x1 = rp[3], y1 = rp[4], z1 = rp[5];
        float r20 = fmaf(x0, x0, fmaf(y0, y0, z0 * z0));
        float r21 = fmaf(x1, x1, fmaf(y1, y1, z1 * z1));
        g_refpack[2 * p + 0] = make_float4(x0, y0, z0, r20);
        g_refpack[2 * p + 1] = make_float4(x1, y1, z1, r21);
        g_refA[p] = make_float4(x0, x1, y0, y1);
        g_refB[p] = make_float4(z0, z1, r20, r21);
    }
}

// ---------------- 64x64 transpose, 128 threads (8 LDG in flight) ----------
template <int R, int N, bool TO_FEAT>
__global__ void transpose64(const float *__restrict__ src) {
    __shared__ float tile[64][65];
    float *dstg = TO_FEAT ? g_featT : g_seedT;
    const int n0 = blockIdx.x * 64, r0 = blockIdx.y * 64, b = blockIdx.z;
    const int tx = threadIdx.x, ty = threadIdx.y;  // (16,8)
    const float *s = src + (size_t)b * R * N;
    float *d = dstg + (size_t)b * N * R;
    float4 v[8];
#pragma unroll
    for (int j = 0; j < 8; j++)
        v[j] = *(const float4 *)(s + (size_t)(r0 + ty + j * 8) * N + n0 + tx * 4);
#pragma unroll
    for (int j = 0; j < 8; j++) {
        tile[ty + j * 8][tx * 4 + 0] = v[j].x;
        tile[ty + j * 8][tx * 4 + 1] = v[j].y;
        tile[ty + j * 8][tx * 4 + 2] = v[j].z;
        tile[ty + j * 8][tx * 4 + 3] = v[j].w;
    }
    __syncthreads();
#pragma unroll
    for (int j = 0; j < 8; j++) {
        const int n = ty + j * 8;
        float4 o = make_float4(f2tf32(tile[tx * 4 + 0][n]),
                               f2tf32(tile[tx * 4 + 1][n]),
                               f2tf32(tile[tx * 4 + 2][n]),
                               f2tf32(tile[tx * 4 + 3][n]));
        *(float4 *)(d + (size_t)(n0 + n) * R + r0 + tx * 4) = o;
    }
}

// ---------------- NN pass A: packed min, 4 queries/thread ------------------
// Refs broadcast from smem (uniform index -> free port); per-thread private
// query coeffs. Exact same per-(query,ref) FMA chain as before.
__global__ void nn_minpass(const float *__restrict__ query) {
    __shared__ float4 spA[PAIRS_PER_SPLIT];
    __shared__ float4 spB[PAIRS_PER_SPLIT];
    const int b  = blockIdx.z;
    const int sp = blockIdx.y;
    const int qb = blockIdx.x * (256 * QPT);
    const int t  = threadIdx.x;

    spA[t] = g_refA[(b * NC / 2) + sp * PAIRS_PER_SPLIT + t];
    spB[t] = g_refB[(b * NC / 2) + sp * PAIRS_PER_SPLIT + t];

    float2 ax[QPT], ay[QPT], az[QPT];
#pragma unroll
    for (int q = 0; q < QPT; q++) {
        const float *qp = query + ((size_t)b * SS + qb + q * 256 + t) * 3;
        float vx = -2.f * qp[0], vy = -2.f * qp[1], vz = -2.f * qp[2];
        ax[q] = make_float2(vx, vx);
        ay[q] = make_float2(vy, vy);
        az[q] = make_float2(vz, vz);
    }
    __syncthreads();

    float best[QPT];
    int   win[QPT];
#pragma unroll
    for (int q = 0; q < QPT; q++) { best[q] = CUDART_INF_F; win[q] = 0; }

#pragma unroll
    for (int w = 0; w < WINS_PER_SPLIT; w++) {
        float2 wm[QPT];
#pragma unroll
        for (int q = 0; q < QPT; q++) wm[q] = make_float2(CUDART_INF_F, CUDART_INF_F);
#pragma unroll 8
        for (int i = 0; i < WREFS / 2; i++) {
            float4 A = spA[w * (WREFS / 2) + i];
            float4 B = spB[w * (WREFS / 2) + i];
            float2 xp = make_float2(A.x, A.y);
            float2 yp = make_float2(A.z, A.w);
            float2 zp = make_float2(B.x, B.y);
            float2 rp = make_float2(B.z, B.w);
#pragma unroll
            for (int q = 0; q < QPT; q++) {
                float2 d = ffma2(ax[q], xp, ffma2(ay[q], yp, ffma2(az[q], zp, rp)));
                wm[q].x = fminf(wm[q].x, d.x);
                wm[q].y = fminf(wm[q].y, d.y);
            }
        }
#pragma unroll
        for (int q = 0; q < QPT; q++) {
            float m = fminf(wm[q].x, wm[q].y);
            if (m < best[q]) { best[q] = m; win[q] = w; }
        }
    }
#pragma unroll
    for (int q = 0; q < QPT; q++) {
        g_pd2 [sp * BS + b * SS + qb + q * 256 + t] = best[q];
        g_pwin[sp * BS + b * SS + qb + q * 256 + t] = win[q];
    }
}

// ---------------- NN resolve: warp per query, coalesced -------------------
__global__ void nn_resolve(const float *__restrict__ query) {
    const int gq   = blockIdx.x * 8 + (threadIdx.x >> 5);  // < BS
    const int lane = threadIdx.x & 31;
    const int b    = gq / SS;

    float best = CUDART_INF_F;
    int wstart = 0;
#pragma unroll
    for (int sp = 0; sp < NSPLIT; sp++) {
        float d = g_pd2[sp * BS + gq];
        if (d < best) { best = d; wstart = sp * REFS_PER_SPLIT + g_pwin[sp * BS + gq] * WREFS; }
    }
    const float *qp = query + (size_t)gq * 3;
    const float ax = -2.f * qp[0], ay = -2.f * qp[1], az = -2.f * qp[2];

    float4 r0 = g_refpack[b * NC + wstart + lane * 2];
    float4 r1 = g_refpack[b * NC + wstart + lane * 2 + 1];
    float d0 = fmaf(ax, r0.x, fmaf(ay, r0.y, fmaf(az, r0.z, r0.w)));
    float d1 = fmaf(ax, r1.x, fmaf(ay, r1.y, fmaf(az, r1.z, r1.w)));

    unsigned cand = 0xFFFFFFFFu;
    if (d1 == best) cand = lane * 2 + 1;
    if (d0 == best) cand = lane * 2;          // prefer earlier
    unsigned m = __reduce_min_sync(0xFFFFFFFFu, cand);
    if (lane == 0) g_idx[gq] = wstart + (int)m;
}

// ---------------- warp-MMA tf32 fused GEMM, 512 threads, 3-stage ----------
// (R16-proven: CTA 128m x 128s, 16 warps, warp tile 32x32)
#define W_TILE  (128 * 128)
#define X_TILE  (128 * 128)
#define STAGE   (W_TILE + X_TILE)    // 32768
#define NCH     24
#define NSTAGE  3

__global__ void __launch_bounds__(512, 1)
gemm_mma(float *__restrict__ out) {
    extern __shared__ char dsm[];
    __shared__ int   sidx[128];
    __shared__ float sbias[128];

    const int b   = blockIdx.z;
    const int m0  = blockIdx.y * 128;
    const int s0  = blockIdx.x * 128;
    const int tid = threadIdx.x;
    const int wid = tid >> 5, lane = tid & 31;

    const uint32_t base = smem_u32(dsm);

    if (tid < 128) {
        sidx[tid]  = g_idx[b * SS + s0 + tid];
        sbias[tid] = g_bias[m0 + tid];
    }
    __syncthreads();

    const float *seedTb = g_seedT + (size_t)b * SS * CSD;
    const float *featTb = g_featT + (size_t)b * NC * CCH;

    const int lrow = tid >> 2;
    const int lch  = (tid & 3) * 2;
    const int xidx = sidx[lrow];
    const uint32_t woff = lrow * 128;
    const int lsx = lrow & 7;

    auto load_stage = [&](int c) {
        const int st = c % NSTAGE;
        const int k0 = c * 32;
        const uint32_t wb = base + st * STAGE;
        const uint32_t xb = wb + W_TILE;
        {
            const float *src = g_Acat + (size_t)(m0 + lrow) * KTOT + k0 + lch * 4;
#pragma unroll
            for (int i = 0; i < 2; i++) {
                int ch = lch + i;
                cp16(wb + woff + ((ch ^ lsx) << 4), src + i * 4);
            }
        }
        {
            const float *src = (k0 < 256)
                ? seedTb + (size_t)(s0 + lrow) * CSD + k0 + lch * 4
                : featTb + (size_t)xidx * CCH + (k0 - 256) + lch * 4;
#pragma unroll
            for (int i = 0; i < 2; i++) {
                int ch = lch + i;
                cp16(xb + woff + ((ch ^ lsx) << 4), src + i * 4);
            }
        }
        cp_commit();
    };

    const int td    = lane >> 3;
    const int a_row = (td & 1) * 8 + (lane & 7);
    const int a_ch  = td >> 1;
    const int b_row = (td >> 1) * 8 + (lane & 7);
    const int b_ch  = td & 1;
    const int sxa = a_row & 7;
    const int sxb = b_row & 7;
    const int wm0 = (wid & 3) * 32;
    const int ws0 = (wid >> 2) * 32;
    uint32_t aoff[2], boff[2];
#pragma unroll
    for (int fi = 0; fi < 2; fi++) aoff[fi] = (wm0 + fi * 16 + a_row) * 128;
#pragma unroll
    for (int fjh = 0; fjh < 2; fjh++) boff[fjh] = (ws0 + fjh * 16 + b_row) * 128;

    float acc[2][4][4];
#pragma unroll
    for (int i = 0; i < 2; i++)
#pragma unroll
        for (int j = 0; j < 4; j++)
#pragma unroll
            for (int r = 0; r < 4; r++) acc[i][j][r] = 0.f;

    load_stage(0);
    load_stage(1);

    for (int c = 0; c < NCH; c++) {
        __syncthreads();
        if (c + 2 < NCH) { load_stage(c + 2); cp_waitN<2>(); }
        else if (c + 1 < NCH) cp_waitN<1>();
        else cp_waitN<0>();
        __syncthreads();

        const int st = c % NSTAGE;
        const uint32_t wb = base + st * STAGE;
        const uint32_t xb = wb + W_TILE;

#pragma unroll
        for (int ks = 0; ks < 4; ks++) {
            const uint32_t cha = ((2 * ks + a_ch) ^ sxa) << 4;
            const uint32_t chb = ((2 * ks + b_ch) ^ sxb) << 4;
            uint32_t areg[2][4];
#pragma unroll
            for (int fi = 0; fi < 2; fi++)
                ldsm4(areg[fi][0], areg[fi][1], areg[fi][2], areg[fi][3],
                      wb + aoff[fi] + cha);
            uint32_t breg[8];
#pragma unroll
            for (int fjh = 0; fjh < 2; fjh++)
                ldsm4(breg[fjh * 4 + 0], breg[fjh * 4 + 1],
                      breg[fjh * 4 + 2], breg[fjh * 4 + 3],
                      xb + boff[fjh] + chb);
#pragma unroll
            for (int fi = 0; fi < 2; fi++)
#pragma unroll
                for (int fj = 0; fj < 4; fj++)
                    mma_tf32(acc[fi][fj], areg[fi], breg + fj * 2);
        }
    }

    // ---- epilogue
#pragma unroll
    for (int fi = 0; fi < 2; fi++) {
        const int ml = wm0 + fi * 16 + (lane >> 2);
        const int mh = ml + 8;
        const float bl = sbias[ml], bh = sbias[mh];
        float *olo = out + ((size_t)b * CSD + m0 + ml) * SS + s0;
        float *ohi = out + ((size_t)b * CSD + m0 + mh) * SS + s0;
#pragma unroll
        for (int fj = 0; fj < 4; fj++) {
            const int s = ws0 + fj * 8 + 2 * (lane & 3);
            *(float2 *)(olo + s) = make_float2(acc[fi][fj][0] + bl, acc[fi][fj][1] + bl);
            *(float2 *)(ohi + s) = make_float2(acc[fi][fj][2] + bh, acc[fi][fj][3] + bh);
        }
    }
}

// ---------------- launch (nn_minpass 4th -> gets profiled) ----------------
extern "C" void kernel_launch(void *const *d_in, const int *in_sizes, int n_in,
                              void *d_out, int out_size) {
    const float *query  = (const float *)d_in[0];
    const float *refxyz = (const float *)d_in[1];
    const float *reffeat= (const float *)d_in[2];
    const float *seed   = (const float *)d_in[3];
    const float *Wsp    = (const float *)d_in[4];
    const float *bseed  = (const float *)d_in[5];
    const float *Wcp    = (const float *)d_in[6];
    const float *bconc  = (const float *)d_in[7];
    float *out = (float *)d_out;

    cudaFuncSetAttribute(gemm_mma, cudaFuncAttributeMaxDynamicSharedMemorySize,
                         NSTAGE * STAGE);

    prep_weights<<<32, 512>>>(Wcp, Wsp, bseed, bconc);
    refpack_kernel<<<(BB * NC / 2 + 255) / 256, 256>>>(refxyz);
    transpose64<CCH, NC, true><<<dim3(NC / 64, CCH / 64, BB), dim3(16, 8)>>>(reffeat);
    nn_minpass<<<dim3(SS / (256 * QPT), NSPLIT, BB), 256>>>(query);
    transpose64<CSD, SS, false><<<dim3(SS / 64, CSD / 64, BB), dim3(16, 8)>>>(seed);
    nn_resolve<<<BS / 8, 256>>>(query);
    gemm_mma<<<dim3(SS / 128, CSD / 128, BB), 512, NSTAGE * STAGE>>>(out);
}